// round 16
// baseline (speedup 1.0000x reference)
#include <cuda_runtime.h>
#include <cuda_fp16.h>
#include <cstdint>

#define BATCH 4
#define SEQ   2048
#define CH    1024
#define NHEAD 16
#define HDIM  64
#define LOG2E 1.4426950408889634f

// Scratch (allocation-free rule: __device__ globals). All operands fp16.
// q,k: [b,h,t,d]; v: [b,h,d,t] (transposed for PV ldmatrix).
__device__ __half g_q16[BATCH * NHEAD * SEQ * HDIM];
__device__ __half g_k16[BATCH * NHEAD * SEQ * HDIM];
__device__ __half g_v16[BATCH * NHEAD * HDIM * SEQ];
__device__ __half g_att16[BATCH * SEQ * CH];     // [b,t,c]
__device__ __half g_x16 [BATCH * SEQ * CH];      // x
__device__ __half g_wa16[3 * CH * CH];           // w_attn^T: [3072][1024]
__device__ __half g_wp16[CH * CH];               // w_proj^T: [1024][1024]

#define MMA_F16(d, a, b)                                                   \
    asm volatile(                                                          \
        "mma.sync.aligned.m16n8k16.row.col.f32.f16.f16.f32 "               \
        "{%0,%1,%2,%3},{%4,%5,%6,%7},{%8,%9},{%0,%1,%2,%3};"               \
        : "+f"((d)[0]), "+f"((d)[1]), "+f"((d)[2]), "+f"((d)[3])           \
        : "r"((a)[0]), "r"((a)[1]), "r"((a)[2]), "r"((a)[3]),              \
          "r"((b)[0]), "r"((b)[1]))

#define LDM_X4(r, addr)                                                    \
    asm volatile("ldmatrix.sync.aligned.m8n8.x4.shared.b16 "               \
                 "{%0,%1,%2,%3}, [%4];"                                    \
                 : "=r"((r)[0]), "=r"((r)[1]), "=r"((r)[2]), "=r"((r)[3])  \
                 : "r"(addr))

#define CP_ASYNC16(dst_u32, src_ptr)                                       \
    asm volatile("cp.async.cg.shared.global [%0], [%1], 16;"               \
                 :: "r"(dst_u32), "l"(src_ptr))
#define CP_COMMIT() asm volatile("cp.async.commit_group;")
#define CP_WAIT(N)  asm volatile("cp.async.wait_group %0;" :: "n"(N))

#define MBAR_INIT(addr, cnt)                                               \
    asm volatile("mbarrier.init.shared::cta.b64 [%0], %1;"                 \
                 :: "r"(addr), "r"((uint32_t)(cnt)) : "memory")
#define MBAR_ARRIVE(addr)                                                  \
    asm volatile("{\n\t.reg .b64 t;\n\t"                                   \
                 "mbarrier.arrive.shared::cta.b64 t, [%0];\n\t}"           \
                 :: "r"(addr) : "memory")
#define CPA_MBAR_ARRIVE(addr)                                              \
    asm volatile("cp.async.mbarrier.arrive.noinc.shared::cta.b64 [%0];"    \
                 :: "r"(addr) : "memory")

__device__ __forceinline__ void mbar_wait(uint32_t mbar, uint32_t parity) {
    asm volatile(
        "{\n\t.reg .pred P;\n\t"
        "W_%=:\n\t"
        "mbarrier.try_wait.parity.acquire.cta.shared::cta.b64 P, [%0], %1, 0x989680;\n\t"
        "@!P bra W_%=;\n\t"
        "}" :: "r"(mbar), "r"(parity) : "memory");
}

__device__ __forceinline__ uint32_t smem_u32(const void* p) {
    return (uint32_t)__cvta_generic_to_shared(p);
}

__device__ __forceinline__ uint32_t packh2(float a, float b) {
    __half2 h = __floats2half2_rn(a, b);
    return *reinterpret_cast<uint32_t*>(&h);
}

// two fp16 exp2 in one MUFU op
__device__ __forceinline__ uint32_t ex2h2(uint32_t x) {
    uint32_t r;
    asm("ex2.approx.f16x2 %0, %1;" : "=r"(r) : "r"(x));
    return r;
}

// ---------------------------------------------------------------------------
// Prologue converts (fp32 -> fp16)
// ---------------------------------------------------------------------------
__global__ void cvt_x_kernel(const float* __restrict__ src, int n4)
{
    int i = blockIdx.x * blockDim.x + threadIdx.x;
    if (i < n4) {
        float4 v = reinterpret_cast<const float4*>(src)[i];
        __half2 h0 = __floats2half2_rn(v.x, v.y);
        __half2 h1 = __floats2half2_rn(v.z, v.w);
        reinterpret_cast<__half2*>(g_x16)[2 * i]     = h0;
        reinterpret_cast<__half2*>(g_x16)[2 * i + 1] = h1;
    }
}

// Transpose + fp16: src [CH][N] -> dst [N][CH]
__global__ void cvt_T_kernel(const float* __restrict__ src, int sel, int N)
{
    __shared__ float tile[32][33];
    __half* dst = (sel == 1) ? g_wa16 : g_wp16;
    int n0 = blockIdx.x * 32, k0 = blockIdx.y * 32;
    int tx = threadIdx.x, ty = threadIdx.y;  // 32 x 8
#pragma unroll
    for (int i = 0; i < 4; i++)
        tile[ty + 8 * i][tx] = src[(size_t)(k0 + ty + 8 * i) * N + n0 + tx];
    __syncthreads();
#pragma unroll
    for (int i = 0; i < 2; i++) {
        int nl = ty + i * 8 + (tx >> 4) * 16;
        int kc = (tx & 15) * 2;
        __half2 h = __floats2half2_rn(tile[kc][nl], tile[kc + 1][nl]);
        *reinterpret_cast<__half2*>(dst + (size_t)(n0 + nl) * CH + k0 + kc) = h;
    }
}

// ---------------------------------------------------------------------------
// FP16 GEMM core (round-13 proven): block 128x128, BK=64, 8 warps (2x4),
// 3-stage mbarrier producer/consumer ring + register double-buffered A frags.
// ---------------------------------------------------------------------------
#define GP 72
#define GROWB (GP * 2)
#define GBUFB (128 * GROWB)
#define NSTAGE 3
#define GEMM_SMEM (2 * NSTAGE * GBUFB + 64)

__device__ __forceinline__ void gemm_issue_loads(
    const __half* __restrict__ A, const __half* __restrict__ B,
    int m0, int n0, int k0, uint32_t sA, uint32_t sB, int tid)
{
#pragma unroll
    for (int it = 0; it < 4; it++) {
        int idx = it * 256 + tid;
        int row = idx >> 3, c = idx & 7;
        CP_ASYNC16(sA + row * GROWB + c * 16,
                   A + (size_t)(m0 + row) * CH + k0 + c * 8);
    }
#pragma unroll
    for (int it = 0; it < 4; it++) {
        int idx = it * 256 + tid;
        int row = idx >> 3, c = idx & 7;
        CP_ASYNC16(sB + row * GROWB + c * 16,
                   B + (size_t)(n0 + row) * CH + k0 + c * 8);
    }
}

__device__ __forceinline__ void f16_gemm_tile(
    const __half* __restrict__ A, const __half* __restrict__ B,
    int m0, int n0,
    float acc[4][4][4],
    uint32_t sbase, int tid)
{
    const int lane  = tid & 31;
    const int wid   = tid >> 5;
    const int wm    = wid & 1;
    const int wn    = wid >> 1;
    const int l16   = lane & 15;
    const int lane8 = lane & 7;

    const uint32_t sA0 = sbase;
    const uint32_t sB0 = sbase + NSTAGE * GBUFB;
    const uint32_t mbF = sbase + 2 * NSTAGE * GBUFB;
    const uint32_t mbE = mbF + 24;

    const uint32_t a_lm =
        ((wm * 64 + l16) * GP + (lane >> 4) * 8) * 2;
    const uint32_t b_lm =
        ((wn * 32 + (lane >> 4) * 8 + lane8) * GP +
         ((lane >> 3) & 1) * 8) * 2;

    if (tid == 0) {
#pragma unroll
        for (int i = 0; i < NSTAGE; i++) {
            MBAR_INIT(mbF + i * 8, 256);
            MBAR_INIT(mbE + i * 8, 8);
        }
    }
    __syncthreads();

    gemm_issue_loads(A, B, m0, n0, 0, sA0, sB0, tid);
    CPA_MBAR_ARRIVE(mbF + 0);
    gemm_issue_loads(A, B, m0, n0, 64, sA0 + GBUFB, sB0 + GBUFB, tid);
    CPA_MBAR_ARRIVE(mbF + 8);

    const int nk = CH / 64;   // 16
    int s = 0;  uint32_t fp = 0;
    int s2 = 2;
    int cc = 0; uint32_t ep = 0;

    for (int ki = 0; ki < nk; ki++) {
        mbar_wait(mbF + s * 8, fp);

        const uint32_t Ab = sA0 + s * GBUFB;
        const uint32_t Bb = sB0 + s * GBUFB;

        uint32_t af[2][4][4];
#pragma unroll
        for (int mt = 0; mt < 4; mt++)
            LDM_X4(af[0][mt], Ab + a_lm + mt * 2304);

#pragma unroll
        for (int ks = 0; ks < 4; ks++) {
            const int cur = ks & 1;
            uint32_t bf[2][4];
            LDM_X4(bf[0], Bb + b_lm + ks * 32);
            LDM_X4(bf[1], Bb + b_lm + 2304 + ks * 32);
            if (ks < 3) {
#pragma unroll
                for (int mt = 0; mt < 4; mt++)
                    LDM_X4(af[cur ^ 1][mt],
                           Ab + a_lm + mt * 2304 + (ks + 1) * 32);
            }
#pragma unroll
            for (int mt = 0; mt < 4; mt++) {
#pragma unroll
                for (int nt2 = 0; nt2 < 2; nt2++) {
                    MMA_F16(acc[mt][2 * nt2],     af[cur][mt], &bf[nt2][0]);
                    MMA_F16(acc[mt][2 * nt2 + 1], af[cur][mt], &bf[nt2][2]);
                }
            }
        }

        if (ki + 2 < nk) {
            if (ki >= 1) {
                mbar_wait(mbE + s2 * 8, ep);
                cc++; if (cc == 3) { cc = 0; ep ^= 1; }
            }
            gemm_issue_loads(A, B, m0, n0, (ki + 2) * 64,
                             sA0 + s2 * GBUFB, sB0 + s2 * GBUFB, tid);
            CPA_MBAR_ARRIVE(mbF + s2 * 8);
        }

        __syncwarp();
        if (lane == 0) MBAR_ARRIVE(mbE + s * 8);

        s = (s + 1 == NSTAGE) ? 0 : s + 1;
        if (s == 0) fp ^= 1;
        s2 = (s2 + 1 == NSTAGE) ? 0 : s2 + 1;
    }
}

// ---------------------------------------------------------------------------
// Kernel 1: QKV GEMM (round-13 proven epilogues).
// ---------------------------------------------------------------------------
#define VPS 144

__global__ __launch_bounds__(256, 2) void qkv_gemm_kernel(
    const float* __restrict__ bias)
{
    extern __shared__ float smg[];
    const uint32_t sbase = smem_u32(smg);
    const int tid = threadIdx.x;
    const int m0 = blockIdx.y * 128;
    const int n0 = blockIdx.x * 128;

    float acc[4][4][4];
#pragma unroll
    for (int i = 0; i < 4; i++)
#pragma unroll
        for (int j = 0; j < 4; j++)
#pragma unroll
            for (int q = 0; q < 4; q++) acc[i][j][q] = 0.f;

    f16_gemm_tile(g_x16, g_wa16, m0, n0, acc, sbase, tid);
    __syncthreads();

    const int lane = tid & 31;
    const int wid  = tid >> 5;
    const int wm   = wid & 1;
    const int wn   = wid >> 1;
    const int lr   = lane >> 2;
    const int lc   = lane & 3;

    const int sec = n0 >> 10;
    const float scale = (sec == 0) ? 0.125f * LOG2E : 1.0f;
    const int bb = m0 >> 11;
    const int t0 = m0 & (SEQ - 1);

    if (sec < 2) {
        __half* dst = (sec == 0) ? g_q16 : g_k16;
#pragma unroll
        for (int mt = 0; mt < 4; mt++) {
            int t = t0 + wm * 64 + mt * 16 + lr;
#pragma unroll
            for (int nt = 0; nt < 4; nt++) {
                int c0 = n0 + wn * 32 + nt * 8 + lc * 2;
                float b0 = bias[c0], b1 = bias[c0 + 1];
                int n1 = c0 & (CH - 1);
                int h  = n1 >> 6;
                int d  = n1 & 63;
                __half* p = dst + ((size_t)((bb * NHEAD + h) * SEQ + t)) * HDIM + d;
                *reinterpret_cast<__half2*>(p) =
                    __floats2half2_rn((acc[mt][nt][0] + b0) * scale,
                                      (acc[mt][nt][1] + b1) * scale);
                *reinterpret_cast<__half2*>(p + 8 * HDIM) =
                    __floats2half2_rn((acc[mt][nt][2] + b0) * scale,
                                      (acc[mt][nt][3] + b1) * scale);
            }
        }
    } else {
        __half* smh = reinterpret_cast<__half*>(smg);
#pragma unroll
        for (int mt = 0; mt < 4; mt++) {
            int rm = wm * 64 + mt * 16 + lr;
#pragma unroll
            for (int nt = 0; nt < 4; nt++) {
                int cc = wn * 32 + nt * 8 + lc * 2;
                float b0 = bias[n0 + cc], b1 = bias[n0 + cc + 1];
                smh[cc * VPS + rm]           = __float2half_rn(acc[mt][nt][0] + b0);
                smh[(cc + 1) * VPS + rm]     = __float2half_rn(acc[mt][nt][1] + b1);
                smh[cc * VPS + rm + 8]       = __float2half_rn(acc[mt][nt][2] + b0);
                smh[(cc + 1) * VPS + rm + 8] = __float2half_rn(acc[mt][nt][3] + b1);
            }
        }
        __syncthreads();
        const int l16 = lane & 15;
#pragma unroll
        for (int it = 0; it < 8; it++) {
            int c = wid * 16 + it * 2 + (lane >> 4);
            uint4 val = *reinterpret_cast<uint4*>(&smh[c * VPS + l16 * 8]);
            int n1 = (n0 + c) & (CH - 1);
            int h = n1 >> 6, d = n1 & 63;
            __half* p = g_v16 +
                ((size_t)((bb * NHEAD + h) * HDIM + d)) * SEQ + t0 + l16 * 8;
            *reinterpret_cast<uint4*>(p) = val;
        }
    }
}

// ---------------------------------------------------------------------------
// Kernel 3: output projection
// ---------------------------------------------------------------------------
__global__ __launch_bounds__(256, 2) void proj_gemm_kernel(
    const float* __restrict__ bias, float* __restrict__ out)
{
    extern __shared__ float smg[];
    const uint32_t sbase = smem_u32(smg);
    const int tid = threadIdx.x;
    const int m0 = blockIdx.y * 128;
    const int n0 = blockIdx.x * 128;

    float acc[4][4][4];
#pragma unroll
    for (int i = 0; i < 4; i++)
#pragma unroll
        for (int j = 0; j < 4; j++)
#pragma unroll
            for (int q = 0; q < 4; q++) acc[i][j][q] = 0.f;

    f16_gemm_tile(g_att16, g_wp16, m0, n0, acc, sbase, tid);

    const int lane = tid & 31;
    const int wid  = tid >> 5;
    const int wm   = wid & 1;
    const int wn   = wid >> 1;
    const int lr   = lane >> 2;
    const int lc   = lane & 3;

#pragma unroll
    for (int mt = 0; mt < 4; mt++) {
        int r0 = m0 + wm * 64 + mt * 16 + lr;
#pragma unroll
        for (int nt = 0; nt < 4; nt++) {
            int c0 = n0 + wn * 32 + nt * 8 + lc * 2;
            float b0 = bias[c0], b1 = bias[c0 + 1];
            *reinterpret_cast<float2*>(&out[(size_t)r0 * CH + c0]) =
                make_float2(acc[mt][nt][0] + b0, acc[mt][nt][1] + b1);
            *reinterpret_cast<float2*>(&out[(size_t)(r0 + 8) * CH + c0]) =
                make_float2(acc[mt][nt][2] + b0, acc[mt][nt][3] + b1);
        }
    }
}

// ---------------------------------------------------------------------------
// Kernel 2: causal flash attention, fp16 mma m16n8k16, exp2h2 softmax,
// ones-MMA row sums. NEW: 3-stage mbarrier K/V ring (GEMM-proven pattern):
// producer issues tile kt+2 before the consume wait; skew tolerance 1 tile
// with 2 tiles of prefetch in flight.
// ---------------------------------------------------------------------------
#define AP 72
#define AROWB (AP * 2)
#define QBUFB (128 * AROWB)
#define KVBUFB (64 * AROWB)
#define ANSTAGE 3
#define ATTN_SMEM (QBUFB + 2 * ANSTAGE * KVBUFB + 64)

__device__ __forceinline__ void attn_issue_kv(
    const __half* __restrict__ kp, const __half* __restrict__ vp,
    int k0, uint32_t sK, uint32_t sV, int tid)
{
#pragma unroll
    for (int it = 0; it < 2; it++) {
        int idx = it * 256 + tid;
        int row = idx >> 3;
        int c   = idx & 7;
        CP_ASYNC16(sK + row * AROWB + c * 16,
                   kp + (size_t)(k0 + row) * HDIM + c * 8);
        CP_ASYNC16(sV + row * AROWB + c * 16,
                   vp + (size_t)row * SEQ + k0 + c * 8);
    }
}

__global__ __launch_bounds__(256, 2) void attn_kernel()
{
    extern __shared__ float sm[];
    const uint32_t sbase = smem_u32(sm);
    const uint32_t sQs = sbase;
    const uint32_t sKs = sbase + QBUFB;
    const uint32_t sVs = sKs + ANSTAGE * KVBUFB;
    const uint32_t mbF = sVs + ANSTAGE * KVBUFB;   // 3 x 8B
    const uint32_t mbE = mbF + 24;                 // 3 x 8B

    const int tid   = threadIdx.x;
    const int lane  = tid & 31;
    const int wq    = tid >> 5;
    const int lr    = lane >> 2;
    const int lc    = lane & 3;
    const int l16   = lane & 15;
    const int lane8 = lane & 7;

    const int qt = (int)gridDim.x - 1 - (int)blockIdx.x;  // big tiles first
    const int bh = blockIdx.y;
    const int q0 = qt * 128;

    const __half* qp = g_q16 + (size_t)bh * SEQ * HDIM;
    const __half* kp = g_k16 + (size_t)bh * SEQ * HDIM;
    const __half* vp = g_v16 + (size_t)bh * HDIM * SEQ;

    const uint32_t q_lm = sQs +
        ((wq * 16 + l16) * AP + (lane >> 4) * 8) * 2;
    const uint32_t kv_lm =
        (((lane >> 4) * 8 + lane8) * AP + ((lane >> 3) & 1) * 8) * 2;

    if (tid == 0) {
#pragma unroll
        for (int i = 0; i < ANSTAGE; i++) {
            MBAR_INIT(mbF + i * 8, 256);
            MBAR_INIT(mbE + i * 8, 8);
        }
    }
    __syncthreads();

    // Prologue: Q + tile 0 (stage 0), tile 1 (stage 1). nkt >= 2 always.
#pragma unroll
    for (int it = 0; it < 4; it++) {
        int idx = it * 256 + tid;
        int row = idx >> 3;
        int c   = idx & 7;
        CP_ASYNC16(sQs + row * AROWB + c * 16,
                   qp + (size_t)(q0 + row) * HDIM + c * 8);
    }
    attn_issue_kv(kp, vp, 0, sKs, sVs, tid);
    CPA_MBAR_ARRIVE(mbF + 0);
    attn_issue_kv(kp, vp, 64, sKs + KVBUFB, sVs + KVBUFB, tid);
    CPA_MBAR_ARRIVE(mbF + 8);

    uint32_t qf[4][4];

    float o[8][4] = {};
    float m0v = -1e30f, m1v = -1e30f;
    float l0v = 0.f, l1v = 0.f;

    const uint32_t ONES2 = 0x3C003C00u;   // half2(1.0, 1.0)
    uint32_t b_ones[2] = {ONES2, ONES2};

    const int nkt  = 2 * qt + 2;
    const int r_hi = q0 + wq * 16 + 15;

    int s = 0;  uint32_t fp = 0;     // consume stage + parity
    int s2 = 2;                      // produce stage (tile kt+2)
    int cc = 0; uint32_t ep = 0;     // empty-wait parity tracker

    for (int kt = 0; kt < nkt; kt++) {
        const int k0 = kt * 64;

        // Produce tile kt+2 into stage s2 (prior occupant: tile kt-1).
        if (kt + 2 < nkt) {
            if (kt >= 1) {
                mbar_wait(mbE + s2 * 8, ep);
                cc++; if (cc == 3) { cc = 0; ep ^= 1; }
            }
            attn_issue_kv(kp, vp, (kt + 2) * 64,
                          sKs + s2 * KVBUFB, sVs + s2 * KVBUFB, tid);
            CPA_MBAR_ARRIVE(mbF + s2 * 8);
        }

        // Consume tile kt.
        mbar_wait(mbF + s * 8, fp);

        if (kt == 0) {
#pragma unroll
            for (int ks = 0; ks < 4; ks++)
                LDM_X4(qf[ks], q_lm + ks * 32);
        }

        if (k0 <= r_hi) {
            const uint32_t Kb = sKs + s * KVBUFB;
            const uint32_t Vb = sVs + s * KVBUFB;

            // ---- S = Q @ K^T ----
            float sacc[8][4];
#pragma unroll
            for (int nt = 0; nt < 8; nt++)
#pragma unroll
                for (int q = 0; q < 4; q++) sacc[nt][q] = 0.f;

#pragma unroll
            for (int ks = 0; ks < 4; ks++) {
#pragma unroll
                for (int nt2 = 0; nt2 < 4; nt2++) {
                    uint32_t bf[4];
                    LDM_X4(bf, Kb + kv_lm + nt2 * 2304 + ks * 32);
                    MMA_F16(sacc[2 * nt2],     qf[ks], &bf[0]);
                    MMA_F16(sacc[2 * nt2 + 1], qf[ks], &bf[2]);
                }
            }

            // ---- causal mask ----
            if (kt >= 2 * qt) {
                int r0g = q0 + wq * 16 + lr;
#pragma unroll
                for (int nt = 0; nt < 8; nt++) {
                    int c0g = k0 + nt * 8 + 2 * lc;
                    if (c0g     > r0g)     sacc[nt][0] = -1e30f;
                    if (c0g + 1 > r0g)     sacc[nt][1] = -1e30f;
                    if (c0g     > r0g + 8) sacc[nt][2] = -1e30f;
                    if (c0g + 1 > r0g + 8) sacc[nt][3] = -1e30f;
                }
            }

            // ---- online softmax: max reduce (fp32), P via f16x2 ex2 ----
            float rm0 = -1e30f, rm1 = -1e30f;
#pragma unroll
            for (int nt = 0; nt < 8; nt++) {
                rm0 = fmaxf(rm0, fmaxf(sacc[nt][0], sacc[nt][1]));
                rm1 = fmaxf(rm1, fmaxf(sacc[nt][2], sacc[nt][3]));
            }
            rm0 = fmaxf(rm0, __shfl_xor_sync(0xffffffffu, rm0, 1));
            rm0 = fmaxf(rm0, __shfl_xor_sync(0xffffffffu, rm0, 2));
            rm1 = fmaxf(rm1, __shfl_xor_sync(0xffffffffu, rm1, 1));
            rm1 = fmaxf(rm1, __shfl_xor_sync(0xffffffffu, rm1, 2));

            float mn0 = fmaxf(m0v, rm0);
            float mn1 = fmaxf(m1v, rm1);
            float cr0 = exp2f(m0v - mn0);
            float cr1 = exp2f(m1v - mn1);
            m0v = mn0; m1v = mn1;

            uint32_t pf[8][2];
#pragma unroll
            for (int nt = 0; nt < 8; nt++) {
                pf[nt][0] = ex2h2(packh2(sacc[nt][0] - mn0, sacc[nt][1] - mn0));
                pf[nt][1] = ex2h2(packh2(sacc[nt][2] - mn1, sacc[nt][3] - mn1));
            }

#pragma unroll
            for (int nt = 0; nt < 8; nt++) {
                o[nt][0] *= cr0; o[nt][1] *= cr0;
                o[nt][2] *= cr1; o[nt][3] *= cr1;
            }

            // ---- O += P @ V and row sums via ones-MMA ----
            float dsum[4] = {0.f, 0.f, 0.f, 0.f};
#pragma unroll
            for (int ks = 0; ks < 4; ks++) {
                uint32_t a[4];
                a[0] = pf[2 * ks][0];
                a[1] = pf[2 * ks][1];
                a[2] = pf[2 * ks + 1][0];
                a[3] = pf[2 * ks + 1][1];
                MMA_F16(dsum, a, b_ones);
#pragma unroll
                for (int nt2 = 0; nt2 < 4; nt2++) {
                    uint32_t b[4];
                    LDM_X4(b, Vb + kv_lm + nt2 * 2304 + ks * 32);
                    MMA_F16(o[2 * nt2],     a, &b[0]);
                    MMA_F16(o[2 * nt2 + 1], a, &b[2]);
                }
            }
            l0v = l0v * cr0 + dsum[0];
            l1v = l1v * cr1 + dsum[2];
        }

        __syncwarp();
        if (lane == 0) MBAR_ARRIVE(mbE + s * 8);   // warp done with tile kt

        s = (s + 1 == ANSTAGE) ? 0 : s + 1;
        if (s == 0) fp ^= 1;
        s2 = (s2 + 1 == ANSTAGE) ? 0 : s2 + 1;
    }

    // ---- normalize + store to [b,t,c] (fp16: feeds proj) ----
    const int b = bh >> 4, h = bh & 15;
    const int r0g = q0 + wq * 16 + lr;
    const float inv0 = 1.0f / l0v;
    const float inv1 = 1.0f / l1v;
#pragma unroll
    for (int nt = 0; nt < 8; nt++) {
        int cg = h * 64 + nt * 8 + 2 * lc;
        *reinterpret_cast<__half2*>(
            &g_att16[(size_t)(b * SEQ + r0g) * CH + cg]) =
            __floats2half2_rn(o[nt][0] * inv0, o[nt][1] * inv0);
        *reinterpret_cast<__half2*>(
            &g_att16[(size_t)(b * SEQ + r0g + 8) * CH + cg]) =
            __floats2half2_rn(o[nt][2] * inv1, o[nt][3] * inv1);
    }
}

// ---------------------------------------------------------------------------
extern "C" void kernel_launch(void* const* d_in, const int* in_sizes, int n_in,
                              void* d_out, int out_size)
{
    const float* x      = (const float*)d_in[0];
    const float* w_attn = (const float*)d_in[1];
    const float* b_attn = (const float*)d_in[2];
    const float* w_proj = (const float*)d_in[3];
    const float* b_proj = (const float*)d_in[4];
    float* out = (float*)d_out;

    cudaFuncSetAttribute(qkv_gemm_kernel,
                         cudaFuncAttributeMaxDynamicSharedMemorySize, GEMM_SMEM);
    cudaFuncSetAttribute(proj_gemm_kernel,
                         cudaFuncAttributeMaxDynamicSharedMemorySize, GEMM_SMEM);
    cudaFuncSetAttribute(attn_kernel,
                         cudaFuncAttributeMaxDynamicSharedMemorySize, ATTN_SMEM);

    // 0) fp16-convert x; transpose+convert weights to [N][K]
    cvt_x_kernel<<<(BATCH * SEQ * CH / 4 + 255) / 256, 256>>>(x,
        BATCH * SEQ * CH / 4);
    cvt_T_kernel<<<dim3(3 * CH / 32, CH / 32), dim3(32, 8)>>>(w_attn, 1, 3 * CH);
    cvt_T_kernel<<<dim3(CH / 32, CH / 32), dim3(32, 8)>>>(w_proj, 2, CH);

    // 1) QKV GEMM: grid (3072/128, 8192/128)
    qkv_gemm_kernel<<<dim3(24, 64), 256, GEMM_SMEM>>>(b_attn);

    // 2) Attention: grid (16 q-tiles, B*NH)
    attn_kernel<<<dim3(16, BATCH * NHEAD), 256, ATTN_SMEM>>>();

    // 3) Projection: grid (1024/128, 8192/128)
    proj_gemm_kernel<<<dim3(8, 64), 256, GEMM_SMEM>>>(b_proj, out);
}

// round 17
// speedup vs baseline: 1.0287x; 1.0287x over previous
#include <cuda_runtime.h>
#include <cuda_fp16.h>
#include <cstdint>

#define BATCH 4
#define SEQ   2048
#define CH    1024
#define NHEAD 16
#define HDIM  64
#define LOG2E 1.4426950408889634f

// Scratch (allocation-free rule: __device__ globals). All operands fp16.
// q,k: [b,h,t,d]; v: [b,h,d,t] (transposed for PV ldmatrix).
__device__ __half g_q16[BATCH * NHEAD * SEQ * HDIM];
__device__ __half g_k16[BATCH * NHEAD * SEQ * HDIM];
__device__ __half g_v16[BATCH * NHEAD * HDIM * SEQ];
__device__ __half g_att16[BATCH * SEQ * CH];     // [b,t,c]
__device__ __half g_x16 [BATCH * SEQ * CH];      // x
__device__ __half g_wa16[3 * CH * CH];           // w_attn^T: [3072][1024]
__device__ __half g_wp16[CH * CH];               // w_proj^T: [1024][1024]

#define MMA_F16(d, a, b)                                                   \
    asm volatile(                                                          \
        "mma.sync.aligned.m16n8k16.row.col.f32.f16.f16.f32 "               \
        "{%0,%1,%2,%3},{%4,%5,%6,%7},{%8,%9},{%0,%1,%2,%3};"               \
        : "+f"((d)[0]), "+f"((d)[1]), "+f"((d)[2]), "+f"((d)[3])           \
        : "r"((a)[0]), "r"((a)[1]), "r"((a)[2]), "r"((a)[3]),              \
          "r"((b)[0]), "r"((b)[1]))

#define LDM_X4(r, addr)                                                    \
    asm volatile("ldmatrix.sync.aligned.m8n8.x4.shared.b16 "               \
                 "{%0,%1,%2,%3}, [%4];"                                    \
                 : "=r"((r)[0]), "=r"((r)[1]), "=r"((r)[2]), "=r"((r)[3])  \
                 : "r"(addr))

#define CP_ASYNC16(dst_u32, src_ptr)                                       \
    asm volatile("cp.async.cg.shared.global [%0], [%1], 16;"               \
                 :: "r"(dst_u32), "l"(src_ptr))
#define CP_COMMIT() asm volatile("cp.async.commit_group;")
#define CP_WAIT(N)  asm volatile("cp.async.wait_group %0;" :: "n"(N))

#define MBAR_INIT(addr, cnt)                                               \
    asm volatile("mbarrier.init.shared::cta.b64 [%0], %1;"                 \
                 :: "r"(addr), "r"((uint32_t)(cnt)) : "memory")
#define MBAR_ARRIVE(addr)                                                  \
    asm volatile("{\n\t.reg .b64 t;\n\t"                                   \
                 "mbarrier.arrive.shared::cta.b64 t, [%0];\n\t}"           \
                 :: "r"(addr) : "memory")
#define CPA_MBAR_ARRIVE(addr)                                              \
    asm volatile("cp.async.mbarrier.arrive.noinc.shared::cta.b64 [%0];"    \
                 :: "r"(addr) : "memory")

__device__ __forceinline__ void mbar_wait(uint32_t mbar, uint32_t parity) {
    asm volatile(
        "{\n\t.reg .pred P;\n\t"
        "W_%=:\n\t"
        "mbarrier.try_wait.parity.acquire.cta.shared::cta.b64 P, [%0], %1, 0x989680;\n\t"
        "@!P bra W_%=;\n\t"
        "}" :: "r"(mbar), "r"(parity) : "memory");
}

__device__ __forceinline__ uint32_t smem_u32(const void* p) {
    return (uint32_t)__cvta_generic_to_shared(p);
}

__device__ __forceinline__ uint32_t packh2(float a, float b) {
    __half2 h = __floats2half2_rn(a, b);
    return *reinterpret_cast<uint32_t*>(&h);
}

// two fp16 exp2 in one MUFU op
__device__ __forceinline__ uint32_t ex2h2(uint32_t x) {
    uint32_t r;
    asm("ex2.approx.f16x2 %0, %1;" : "=r"(r) : "r"(x));
    return r;
}

// ---------------------------------------------------------------------------
// Unified prologue convert: one launch does x-convert + both weight
// transposes (block-range dispatch), overlapping their memory traffic.
//   blocks [0, XB)            : x  fp32->fp16 (float4 per thread)
//   blocks [XB, XB+WAB)       : w_attn transpose+convert (32x32 tiles)
//   blocks [XB+WAB, +WPB)     : w_proj transpose+convert
// ---------------------------------------------------------------------------
#define XN4  (BATCH * SEQ * CH / 4)       // 2097152 float4s
#define XB   (XN4 / 256)                  // 8192 blocks
#define WAB  ((3 * CH / 32) * (CH / 32))  // 96*32 = 3072 blocks
#define WPB  ((CH / 32) * (CH / 32))      // 32*32 = 1024 blocks

__global__ __launch_bounds__(256) void cvt_all_kernel(
    const float* __restrict__ x,
    const float* __restrict__ w_attn,
    const float* __restrict__ w_proj)
{
    int bid = blockIdx.x;
    if (bid < XB) {
        int i = bid * 256 + threadIdx.x;
        float4 v = reinterpret_cast<const float4*>(x)[i];
        __half2 h0 = __floats2half2_rn(v.x, v.y);
        __half2 h1 = __floats2half2_rn(v.z, v.w);
        reinterpret_cast<__half2*>(g_x16)[2 * i]     = h0;
        reinterpret_cast<__half2*>(g_x16)[2 * i + 1] = h1;
        return;
    }
    // transpose jobs: treat 256 threads as (tx=0..31, ty=0..7)
    __shared__ float tile[32][33];
    const float* src;
    __half* dst;
    int N, tb;
    if (bid < XB + WAB) {
        tb = bid - XB; src = w_attn; dst = g_wa16; N = 3 * CH;
    } else {
        tb = bid - XB - WAB; src = w_proj; dst = g_wp16; N = CH;
    }
    int nblk = N / 32;
    int n0 = (tb % nblk) * 32;
    int k0 = (tb / nblk) * 32;
    int tx = threadIdx.x & 31;
    int ty = threadIdx.x >> 5;
#pragma unroll
    for (int i = 0; i < 4; i++)
        tile[ty + 8 * i][tx] = src[(size_t)(k0 + ty + 8 * i) * N + n0 + tx];
    __syncthreads();
#pragma unroll
    for (int i = 0; i < 2; i++) {
        int nl = ty + i * 8 + (tx >> 4) * 16;
        int kc = (tx & 15) * 2;
        __half2 h = __floats2half2_rn(tile[kc][nl], tile[kc + 1][nl]);
        *reinterpret_cast<__half2*>(dst + (size_t)(n0 + nl) * CH + k0 + kc) = h;
    }
}

// ---------------------------------------------------------------------------
// FP16 GEMM core (round-13 proven): block 128x128, BK=64, 8 warps (2x4),
// 3-stage mbarrier producer/consumer ring + register double-buffered A frags.
// ---------------------------------------------------------------------------
#define GP 72
#define GROWB (GP * 2)
#define GBUFB (128 * GROWB)
#define NSTAGE 3
#define GEMM_SMEM (2 * NSTAGE * GBUFB + 64)

__device__ __forceinline__ void gemm_issue_loads(
    const __half* __restrict__ A, const __half* __restrict__ B,
    int m0, int n0, int k0, uint32_t sA, uint32_t sB, int tid)
{
#pragma unroll
    for (int it = 0; it < 4; it++) {
        int idx = it * 256 + tid;
        int row = idx >> 3, c = idx & 7;
        CP_ASYNC16(sA + row * GROWB + c * 16,
                   A + (size_t)(m0 + row) * CH + k0 + c * 8);
    }
#pragma unroll
    for (int it = 0; it < 4; it++) {
        int idx = it * 256 + tid;
        int row = idx >> 3, c = idx & 7;
        CP_ASYNC16(sB + row * GROWB + c * 16,
                   B + (size_t)(n0 + row) * CH + k0 + c * 8);
    }
}

__device__ __forceinline__ void f16_gemm_tile(
    const __half* __restrict__ A, const __half* __restrict__ B,
    int m0, int n0,
    float acc[4][4][4],
    uint32_t sbase, int tid)
{
    const int lane  = tid & 31;
    const int wid   = tid >> 5;
    const int wm    = wid & 1;
    const int wn    = wid >> 1;
    const int l16   = lane & 15;
    const int lane8 = lane & 7;

    const uint32_t sA0 = sbase;
    const uint32_t sB0 = sbase + NSTAGE * GBUFB;
    const uint32_t mbF = sbase + 2 * NSTAGE * GBUFB;
    const uint32_t mbE = mbF + 24;

    const uint32_t a_lm =
        ((wm * 64 + l16) * GP + (lane >> 4) * 8) * 2;
    const uint32_t b_lm =
        ((wn * 32 + (lane >> 4) * 8 + lane8) * GP +
         ((lane >> 3) & 1) * 8) * 2;

    if (tid == 0) {
#pragma unroll
        for (int i = 0; i < NSTAGE; i++) {
            MBAR_INIT(mbF + i * 8, 256);
            MBAR_INIT(mbE + i * 8, 8);
        }
    }
    __syncthreads();

    gemm_issue_loads(A, B, m0, n0, 0, sA0, sB0, tid);
    CPA_MBAR_ARRIVE(mbF + 0);
    gemm_issue_loads(A, B, m0, n0, 64, sA0 + GBUFB, sB0 + GBUFB, tid);
    CPA_MBAR_ARRIVE(mbF + 8);

    const int nk = CH / 64;   // 16
    int s = 0;  uint32_t fp = 0;
    int s2 = 2;
    int cc = 0; uint32_t ep = 0;

    for (int ki = 0; ki < nk; ki++) {
        mbar_wait(mbF + s * 8, fp);

        const uint32_t Ab = sA0 + s * GBUFB;
        const uint32_t Bb = sB0 + s * GBUFB;

        uint32_t af[2][4][4];
#pragma unroll
        for (int mt = 0; mt < 4; mt++)
            LDM_X4(af[0][mt], Ab + a_lm + mt * 2304);

#pragma unroll
        for (int ks = 0; ks < 4; ks++) {
            const int cur = ks & 1;
            uint32_t bf[2][4];
            LDM_X4(bf[0], Bb + b_lm + ks * 32);
            LDM_X4(bf[1], Bb + b_lm + 2304 + ks * 32);
            if (ks < 3) {
#pragma unroll
                for (int mt = 0; mt < 4; mt++)
                    LDM_X4(af[cur ^ 1][mt],
                           Ab + a_lm + mt * 2304 + (ks + 1) * 32);
            }
#pragma unroll
            for (int mt = 0; mt < 4; mt++) {
#pragma unroll
                for (int nt2 = 0; nt2 < 2; nt2++) {
                    MMA_F16(acc[mt][2 * nt2],     af[cur][mt], &bf[nt2][0]);
                    MMA_F16(acc[mt][2 * nt2 + 1], af[cur][mt], &bf[nt2][2]);
                }
            }
        }

        if (ki + 2 < nk) {
            if (ki >= 1) {
                mbar_wait(mbE + s2 * 8, ep);
                cc++; if (cc == 3) { cc = 0; ep ^= 1; }
            }
            gemm_issue_loads(A, B, m0, n0, (ki + 2) * 64,
                             sA0 + s2 * GBUFB, sB0 + s2 * GBUFB, tid);
            CPA_MBAR_ARRIVE(mbF + s2 * 8);
        }

        __syncwarp();
        if (lane == 0) MBAR_ARRIVE(mbE + s * 8);

        s = (s + 1 == NSTAGE) ? 0 : s + 1;
        if (s == 0) fp ^= 1;
        s2 = (s2 + 1 == NSTAGE) ? 0 : s2 + 1;
    }
}

// ---------------------------------------------------------------------------
// Kernel 1: QKV GEMM (round-13 proven epilogues).
// ---------------------------------------------------------------------------
#define VPS 144

__global__ __launch_bounds__(256, 2) void qkv_gemm_kernel(
    const float* __restrict__ bias)
{
    extern __shared__ float smg[];
    const uint32_t sbase = smem_u32(smg);
    const int tid = threadIdx.x;
    const int m0 = blockIdx.y * 128;
    const int n0 = blockIdx.x * 128;

    float acc[4][4][4];
#pragma unroll
    for (int i = 0; i < 4; i++)
#pragma unroll
        for (int j = 0; j < 4; j++)
#pragma unroll
            for (int q = 0; q < 4; q++) acc[i][j][q] = 0.f;

    f16_gemm_tile(g_x16, g_wa16, m0, n0, acc, sbase, tid);
    __syncthreads();

    const int lane = tid & 31;
    const int wid  = tid >> 5;
    const int wm   = wid & 1;
    const int wn   = wid >> 1;
    const int lr   = lane >> 2;
    const int lc   = lane & 3;

    const int sec = n0 >> 10;
    const float scale = (sec == 0) ? 0.125f * LOG2E : 1.0f;
    const int bb = m0 >> 11;
    const int t0 = m0 & (SEQ - 1);

    if (sec < 2) {
        __half* dst = (sec == 0) ? g_q16 : g_k16;
#pragma unroll
        for (int mt = 0; mt < 4; mt++) {
            int t = t0 + wm * 64 + mt * 16 + lr;
#pragma unroll
            for (int nt = 0; nt < 4; nt++) {
                int c0 = n0 + wn * 32 + nt * 8 + lc * 2;
                float b0 = bias[c0], b1 = bias[c0 + 1];
                int n1 = c0 & (CH - 1);
                int h  = n1 >> 6;
                int d  = n1 & 63;
                __half* p = dst + ((size_t)((bb * NHEAD + h) * SEQ + t)) * HDIM + d;
                *reinterpret_cast<__half2*>(p) =
                    __floats2half2_rn((acc[mt][nt][0] + b0) * scale,
                                      (acc[mt][nt][1] + b1) * scale);
                *reinterpret_cast<__half2*>(p + 8 * HDIM) =
                    __floats2half2_rn((acc[mt][nt][2] + b0) * scale,
                                      (acc[mt][nt][3] + b1) * scale);
            }
        }
    } else {
        __half* smh = reinterpret_cast<__half*>(smg);
#pragma unroll
        for (int mt = 0; mt < 4; mt++) {
            int rm = wm * 64 + mt * 16 + lr;
#pragma unroll
            for (int nt = 0; nt < 4; nt++) {
                int cc = wn * 32 + nt * 8 + lc * 2;
                float b0 = bias[n0 + cc], b1 = bias[n0 + cc + 1];
                smh[cc * VPS + rm]           = __float2half_rn(acc[mt][nt][0] + b0);
                smh[(cc + 1) * VPS + rm]     = __float2half_rn(acc[mt][nt][1] + b1);
                smh[cc * VPS + rm + 8]       = __float2half_rn(acc[mt][nt][2] + b0);
                smh[(cc + 1) * VPS + rm + 8] = __float2half_rn(acc[mt][nt][3] + b1);
            }
        }
        __syncthreads();
        const int l16 = lane & 15;
#pragma unroll
        for (int it = 0; it < 8; it++) {
            int c = wid * 16 + it * 2 + (lane >> 4);
            uint4 val = *reinterpret_cast<uint4*>(&smh[c * VPS + l16 * 8]);
            int n1 = (n0 + c) & (CH - 1);
            int h = n1 >> 6, d = n1 & 63;
            __half* p = g_v16 +
                ((size_t)((bb * NHEAD + h) * HDIM + d)) * SEQ + t0 + l16 * 8;
            *reinterpret_cast<uint4*>(p) = val;
        }
    }
}

// ---------------------------------------------------------------------------
// Kernel 3: output projection
// ---------------------------------------------------------------------------
__global__ __launch_bounds__(256, 2) void proj_gemm_kernel(
    const float* __restrict__ bias, float* __restrict__ out)
{
    extern __shared__ float smg[];
    const uint32_t sbase = smem_u32(smg);
    const int tid = threadIdx.x;
    const int m0 = blockIdx.y * 128;
    const int n0 = blockIdx.x * 128;

    float acc[4][4][4];
#pragma unroll
    for (int i = 0; i < 4; i++)
#pragma unroll
        for (int j = 0; j < 4; j++)
#pragma unroll
            for (int q = 0; q < 4; q++) acc[i][j][q] = 0.f;

    f16_gemm_tile(g_att16, g_wp16, m0, n0, acc, sbase, tid);

    const int lane = tid & 31;
    const int wid  = tid >> 5;
    const int wm   = wid & 1;
    const int wn   = wid >> 1;
    const int lr   = lane >> 2;
    const int lc   = lane & 3;

#pragma unroll
    for (int mt = 0; mt < 4; mt++) {
        int r0 = m0 + wm * 64 + mt * 16 + lr;
#pragma unroll
        for (int nt = 0; nt < 4; nt++) {
            int c0 = n0 + wn * 32 + nt * 8 + lc * 2;
            float b0 = bias[c0], b1 = bias[c0 + 1];
            *reinterpret_cast<float2*>(&out[(size_t)r0 * CH + c0]) =
                make_float2(acc[mt][nt][0] + b0, acc[mt][nt][1] + b1);
            *reinterpret_cast<float2*>(&out[(size_t)(r0 + 8) * CH + c0]) =
                make_float2(acc[mt][nt][2] + b0, acc[mt][nt][3] + b1);
        }
    }
}

// ---------------------------------------------------------------------------
// Kernel 2: causal flash attention (round-15 proven): fp16 mma m16n8k16,
// 2-stage mbarrier K/V pipeline, ex2.approx.f16x2 softmax, in-register P
// repack, ones-MMA row sums.
// ---------------------------------------------------------------------------
#define AP 72
#define AROWB (AP * 2)
#define QBUFB (128 * AROWB)
#define KVBUFB (64 * AROWB)
#define ATTN_SMEM (QBUFB + 4 * KVBUFB + 32)

__device__ __forceinline__ void attn_issue_kv(
    const __half* __restrict__ kp, const __half* __restrict__ vp,
    int k0, uint32_t sK, uint32_t sV, int tid)
{
#pragma unroll
    for (int it = 0; it < 2; it++) {
        int idx = it * 256 + tid;
        int row = idx >> 3;
        int c   = idx & 7;
        CP_ASYNC16(sK + row * AROWB + c * 16,
                   kp + (size_t)(k0 + row) * HDIM + c * 8);
        CP_ASYNC16(sV + row * AROWB + c * 16,
                   vp + (size_t)row * SEQ + k0 + c * 8);
    }
}

__global__ __launch_bounds__(256, 2) void attn_kernel()
{
    extern __shared__ float sm[];
    const uint32_t sbase = smem_u32(sm);
    const uint32_t sQs = sbase;
    const uint32_t sKs = sbase + QBUFB;
    const uint32_t sVs = sKs + 2 * KVBUFB;
    const uint32_t mbF = sVs + 2 * KVBUFB;
    const uint32_t mbE = mbF + 16;

    const int tid   = threadIdx.x;
    const int lane  = tid & 31;
    const int wq    = tid >> 5;
    const int lr    = lane >> 2;
    const int lc    = lane & 3;
    const int l16   = lane & 15;
    const int lane8 = lane & 7;

    const int qt = (int)gridDim.x - 1 - (int)blockIdx.x;  // big tiles first
    const int bh = blockIdx.y;
    const int q0 = qt * 128;

    const __half* qp = g_q16 + (size_t)bh * SEQ * HDIM;
    const __half* kp = g_k16 + (size_t)bh * SEQ * HDIM;
    const __half* vp = g_v16 + (size_t)bh * HDIM * SEQ;

    const uint32_t q_lm = sQs +
        ((wq * 16 + l16) * AP + (lane >> 4) * 8) * 2;
    const uint32_t kv_lm =
        (((lane >> 4) * 8 + lane8) * AP + ((lane >> 3) & 1) * 8) * 2;

    if (tid == 0) {
        MBAR_INIT(mbF + 0, 256);
        MBAR_INIT(mbF + 8, 256);
        MBAR_INIT(mbE + 0, 8);
        MBAR_INIT(mbE + 8, 8);
    }
    __syncthreads();

#pragma unroll
    for (int it = 0; it < 4; it++) {
        int idx = it * 256 + tid;
        int row = idx >> 3;
        int c   = idx & 7;
        CP_ASYNC16(sQs + row * AROWB + c * 16,
                   qp + (size_t)(q0 + row) * HDIM + c * 8);
    }
    attn_issue_kv(kp, vp, 0, sKs, sVs, tid);
    CPA_MBAR_ARRIVE(mbF + 0);
    attn_issue_kv(kp, vp, 64, sKs + KVBUFB, sVs + KVBUFB, tid);
    CPA_MBAR_ARRIVE(mbF + 8);

    uint32_t qf[4][4];

    float o[8][4] = {};
    float m0v = -1e30f, m1v = -1e30f;
    float l0v = 0.f, l1v = 0.f;

    const uint32_t ONES2 = 0x3C003C00u;   // half2(1.0, 1.0)
    uint32_t b_ones[2] = {ONES2, ONES2};

    const int nkt  = 2 * qt + 2;
    const int r_hi = q0 + wq * 16 + 15;

    for (int kt = 0; kt < nkt; kt++) {
        const int k0 = kt * 64;
        const uint32_t s  = (uint32_t)(kt & 1);
        const uint32_t cp = (uint32_t)((kt >> 1) & 1);

        if (kt >= 1 && kt + 1 < nkt) {
            const uint32_t so = s ^ 1u;
            mbar_wait(mbE + so * 8, (uint32_t)(((kt - 1) >> 1) & 1));
            attn_issue_kv(kp, vp, (kt + 1) * 64,
                          sKs + so * KVBUFB, sVs + so * KVBUFB, tid);
            CPA_MBAR_ARRIVE(mbF + so * 8);
        }

        mbar_wait(mbF + s * 8, cp);

        if (kt == 0) {
#pragma unroll
            for (int ks = 0; ks < 4; ks++)
                LDM_X4(qf[ks], q_lm + ks * 32);
        }

        if (k0 <= r_hi) {
            const uint32_t Kb = sKs + s * KVBUFB;
            const uint32_t Vb = sVs + s * KVBUFB;

            // ---- S = Q @ K^T ----
            float sacc[8][4];
#pragma unroll
            for (int nt = 0; nt < 8; nt++)
#pragma unroll
                for (int q = 0; q < 4; q++) sacc[nt][q] = 0.f;

#pragma unroll
            for (int ks = 0; ks < 4; ks++) {
#pragma unroll
                for (int nt2 = 0; nt2 < 4; nt2++) {
                    uint32_t bf[4];
                    LDM_X4(bf, Kb + kv_lm + nt2 * 2304 + ks * 32);
                    MMA_F16(sacc[2 * nt2],     qf[ks], &bf[0]);
                    MMA_F16(sacc[2 * nt2 + 1], qf[ks], &bf[2]);
                }
            }

            // ---- causal mask ----
            if (kt >= 2 * qt) {
                int r0g = q0 + wq * 16 + lr;
#pragma unroll
                for (int nt = 0; nt < 8; nt++) {
                    int c0g = k0 + nt * 8 + 2 * lc;
                    if (c0g     > r0g)     sacc[nt][0] = -1e30f;
                    if (c0g + 1 > r0g)     sacc[nt][1] = -1e30f;
                    if (c0g     > r0g + 8) sacc[nt][2] = -1e30f;
                    if (c0g + 1 > r0g + 8) sacc[nt][3] = -1e30f;
                }
            }

            // ---- online softmax: max reduce (fp32), P via f16x2 ex2 ----
            float rm0 = -1e30f, rm1 = -1e30f;
#pragma unroll
            for (int nt = 0; nt < 8; nt++) {
                rm0 = fmaxf(rm0, fmaxf(sacc[nt][0], sacc[nt][1]));
                rm1 = fmaxf(rm1, fmaxf(sacc[nt][2], sacc[nt][3]));
            }
            rm0 = fmaxf(rm0, __shfl_xor_sync(0xffffffffu, rm0, 1));
            rm0 = fmaxf(rm0, __shfl_xor_sync(0xffffffffu, rm0, 2));
            rm1 = fmaxf(rm1, __shfl_xor_sync(0xffffffffu, rm1, 1));
            rm1 = fmaxf(rm1, __shfl_xor_sync(0xffffffffu, rm1, 2));

            float mn0 = fmaxf(m0v, rm0);
            float mn1 = fmaxf(m1v, rm1);
            float cr0 = exp2f(m0v - mn0);
            float cr1 = exp2f(m1v - mn1);
            m0v = mn0; m1v = mn1;

            uint32_t pf[8][2];
#pragma unroll
            for (int nt = 0; nt < 8; nt++) {
                pf[nt][0] = ex2h2(packh2(sacc[nt][0] - mn0, sacc[nt][1] - mn0));
                pf[nt][1] = ex2h2(packh2(sacc[nt][2] - mn1, sacc[nt][3] - mn1));
            }

#pragma unroll
            for (int nt = 0; nt < 8; nt++) {
                o[nt][0] *= cr0; o[nt][1] *= cr0;
                o[nt][2] *= cr1; o[nt][3] *= cr1;
            }

            // ---- O += P @ V and row sums via ones-MMA ----
            float dsum[4] = {0.f, 0.f, 0.f, 0.f};
#pragma unroll
            for (int ks = 0; ks < 4; ks++) {
                uint32_t a[4];
                a[0] = pf[2 * ks][0];
                a[1] = pf[2 * ks][1];
                a[2] = pf[2 * ks + 1][0];
                a[3] = pf[2 * ks + 1][1];
                MMA_F16(dsum, a, b_ones);
#pragma unroll
                for (int nt2 = 0; nt2 < 4; nt2++) {
                    uint32_t b[4];
                    LDM_X4(b, Vb + kv_lm + nt2 * 2304 + ks * 32);
                    MMA_F16(o[2 * nt2],     a, &b[0]);
                    MMA_F16(o[2 * nt2 + 1], a, &b[2]);
                }
            }
            l0v = l0v * cr0 + dsum[0];
            l1v = l1v * cr1 + dsum[2];
        }

        __syncwarp();
        if (lane == 0) MBAR_ARRIVE(mbE + s * 8);
    }

    // ---- normalize + store to [b,t,c] (fp16: feeds proj) ----
    const int b = bh >> 4, h = bh & 15;
    const int r0g = q0 + wq * 16 + lr;
    const float inv0 = 1.0f / l0v;
    const float inv1 = 1.0f / l1v;
#pragma unroll
    for (int nt = 0; nt < 8; nt++) {
        int cg = h * 64 + nt * 8 + 2 * lc;
        *reinterpret_cast<__half2*>(
            &g_att16[(size_t)(b * SEQ + r0g) * CH + cg]) =
            __floats2half2_rn(o[nt][0] * inv0, o[nt][1] * inv0);
        *reinterpret_cast<__half2*>(
            &g_att16[(size_t)(b * SEQ + r0g + 8) * CH + cg]) =
            __floats2half2_rn(o[nt][2] * inv1, o[nt][3] * inv1);
    }
}

// ---------------------------------------------------------------------------
extern "C" void kernel_launch(void* const* d_in, const int* in_sizes, int n_in,
                              void* d_out, int out_size)
{
    const float* x      = (const float*)d_in[0];
    const float* w_attn = (const float*)d_in[1];
    const float* b_attn = (const float*)d_in[2];
    const float* w_proj = (const float*)d_in[3];
    const float* b_proj = (const float*)d_in[4];
    float* out = (float*)d_out;

    cudaFuncSetAttribute(qkv_gemm_kernel,
                         cudaFuncAttributeMaxDynamicSharedMemorySize, GEMM_SMEM);
    cudaFuncSetAttribute(proj_gemm_kernel,
                         cudaFuncAttributeMaxDynamicSharedMemorySize, GEMM_SMEM);
    cudaFuncSetAttribute(attn_kernel,
                         cudaFuncAttributeMaxDynamicSharedMemorySize, ATTN_SMEM);

    // 0) single fused convert launch: x + both weight transposes
    cvt_all_kernel<<<XB + WAB + WPB, 256>>>(x, w_attn, w_proj);

    // 1) QKV GEMM: grid (3072/128, 8192/128)
    qkv_gemm_kernel<<<dim3(24, 64), 256, GEMM_SMEM>>>(b_attn);

    // 2) Attention: grid (16 q-tiles, B*NH)
    attn_kernel<<<dim3(16, BATCH * NHEAD), 256, ATTN_SMEM>>>();

    // 3) Projection: grid (1024/128, 8192/128)
    proj_gemm_kernel<<<dim3(8, 64), 256, GEMM_SMEM>>>(b_proj, out);
}